// round 1
// baseline (speedup 1.0000x reference)
#include <cuda_runtime.h>
#include <cuda_bf16.h>
#include <cstdint>

#define UNITS  256
#define FT     128
#define BATCH  32
#define TSTEPS 2048
#define EPS_   0.01f
#define GAMMA_ 0.01f

// Packed M in bf16 pairs along the contraction (state) axis k:
// g_Mpk[kp*UNITS + u] = (bf16(M[2kp][u]) | bf16(M[2kp+1][u]) << 16)
// where M[k][u] = W[k][u] - W[u][k] - gamma * (k==u).
// 128 * 256 * 4 B = 128 KB static device scratch (allowed).
__device__ uint32_t g_Mpk[(UNITS / 2) * UNITS];

__device__ __forceinline__ __nv_bfloat162 u2b(uint32_t v) {
    return *reinterpret_cast<__nv_bfloat162*>(&v);
}

// ---------------------------------------------------------------------------
// Kernel 0: build packed antisymmetric-damped M in bf16
// grid: 128 blocks (kp), 256 threads (u)
// ---------------------------------------------------------------------------
__global__ void prep_M_kernel(const float* __restrict__ W) {
    const int u  = threadIdx.x;   // 0..255
    const int kp = blockIdx.x;    // 0..127
    const int k0 = 2 * kp, k1 = 2 * kp + 1;
    float m0 = W[k0 * UNITS + u] - W[u * UNITS + k0] - (k0 == u ? GAMMA_ : 0.f);
    float m1 = W[k1 * UNITS + u] - W[u * UNITS + k1] - (k1 == u ? GAMMA_ : 0.f);
    __nv_bfloat162 p = __floats2bfloat162_rn(m0, m1);  // .x = m0 (low), .y = m1
    g_Mpk[kp * UNITS + u] = *reinterpret_cast<uint32_t*>(&p);
}

// ---------------------------------------------------------------------------
// Kernel 1: H = x @ V + bias, written in-place into d_out.
// fp32, 128x128 tile per CTA, 8x8 micro-tile per thread, K chunked by 32.
// grid: (UNITS/128=2, 65536/128=512), 256 threads
// ---------------------------------------------------------------------------
#define PT_KC 32
__global__ __launch_bounds__(256) void proj_kernel(const float* __restrict__ X,
                                                   const float* __restrict__ V,
                                                   const float* __restrict__ bias,
                                                   float* __restrict__ H) {
    __shared__ float As[PT_KC][129];   // [k][row]  (transposed x tile, +1 pad)
    __shared__ float Bs[PT_KC][129];   // [k][col]

    const int tid = threadIdx.x;
    const int tx  = tid & 15;          // n direction, 8 cols each
    const int ty  = tid >> 4;          // row direction, 8 rows each
    const int r0  = blockIdx.y * 128;
    const int n0  = blockIdx.x * 128;

    float bv[8];
#pragma unroll
    for (int j = 0; j < 8; j++) bv[j] = __ldg(&bias[n0 + tx * 8 + j]);

    float acc[8][8];
#pragma unroll
    for (int i = 0; i < 8; i++)
#pragma unroll
        for (int j = 0; j < 8; j++) acc[i][j] = 0.f;

    for (int kc = 0; kc < FT; kc += PT_KC) {
        // load x tile: 128 rows x 32 k, transposed into As[k][row]
        {
            const int row   = tid >> 1;
            const int kbase = (tid & 1) * 16;
            const float4* src =
                reinterpret_cast<const float4*>(&X[(size_t)(r0 + row) * FT + kc + kbase]);
#pragma unroll
            for (int i = 0; i < 4; i++) {
                float4 v4 = src[i];
                int kk = kbase + 4 * i;
                As[kk + 0][row] = v4.x;
                As[kk + 1][row] = v4.y;
                As[kk + 2][row] = v4.z;
                As[kk + 3][row] = v4.w;
            }
        }
        // load V tile: 32 k x 128 n into Bs[k][n]
        {
            const int kr = tid >> 3;
            const int cb = (tid & 7) * 16;
            const float4* src =
                reinterpret_cast<const float4*>(&V[(size_t)(kc + kr) * UNITS + n0 + cb]);
#pragma unroll
            for (int i = 0; i < 4; i++) {
                float4 v4 = src[i];
                Bs[kr][cb + 4 * i + 0] = v4.x;
                Bs[kr][cb + 4 * i + 1] = v4.y;
                Bs[kr][cb + 4 * i + 2] = v4.z;
                Bs[kr][cb + 4 * i + 3] = v4.w;
            }
        }
        __syncthreads();

#pragma unroll
        for (int k = 0; k < PT_KC; k++) {
            float a[8], bb[8];
#pragma unroll
            for (int i = 0; i < 8; i++) a[i] = As[k][ty * 8 + i];
#pragma unroll
            for (int j = 0; j < 8; j++) bb[j] = Bs[k][tx * 8 + j];
#pragma unroll
            for (int i = 0; i < 8; i++)
#pragma unroll
                for (int j = 0; j < 8; j++)
                    acc[i][j] = fmaf(a[i], bb[j], acc[i][j]);
        }
        __syncthreads();
    }

#pragma unroll
    for (int i = 0; i < 8; i++) {
        float* dst = &H[(size_t)(r0 + ty * 8 + i) * UNITS + n0 + tx * 8];
        float4 o0, o1;
        o0.x = acc[i][0] + bv[0]; o0.y = acc[i][1] + bv[1];
        o0.z = acc[i][2] + bv[2]; o0.w = acc[i][3] + bv[3];
        o1.x = acc[i][4] + bv[4]; o1.y = acc[i][5] + bv[5];
        o1.z = acc[i][6] + bv[6]; o1.w = acc[i][7] + bv[7];
        reinterpret_cast<float4*>(dst)[0] = o0;
        reinterpret_cast<float4*>(dst)[1] = o1;
    }
}

// ---------------------------------------------------------------------------
// Kernel 2: sequential recurrence, one CTA per batch element.
// 512 threads: thread (c = tid>>8, u = tid&255) owns half of M-column u in
// 64 packed bf16x2 registers. State lives in smem as packed bf16 pairs,
// read as broadcast uint4. HFMA2 main loop, fp32 reduce + tanh + update.
// HS = d_out: holds h_t until step t consumes it, then the state.
// ---------------------------------------------------------------------------
__global__ __launch_bounds__(512, 1) void rnn_kernel(float* __restrict__ HS,
                                                     const float* __restrict__ x0) {
    __shared__ uint32_t sm_sbf[UNITS / 2];  // packed bf16 state pairs
    __shared__ float    sm_part[UNITS];     // c==1 partial sums

    const int tid = threadIdx.x;
    const int u   = tid & (UNITS - 1);
    const int c   = tid >> 8;   // 0 or 1
    const int b   = blockIdx.x;
    float* Hb = HS + (size_t)b * TSTEPS * UNITS;

    // Load this thread's M-column half: coalesced (kp-major layout).
    uint32_t mreg[64];
#pragma unroll
    for (int j = 0; j < 64; j++)
        mreg[j] = g_Mpk[(c * 64 + j) * UNITS + u];

    float s = 0.f, hcur = 0.f;
    if (c == 0) {
        s    = x0[u];
        hcur = Hb[u];
    }
    if (tid < UNITS / 2) {
        __nv_bfloat162 p = __floats2bfloat162_rn(x0[2 * tid], x0[2 * tid + 1]);
        sm_sbf[tid] = *reinterpret_cast<uint32_t*>(&p);
    }
    __syncthreads();

    for (int t = 0; t < TSTEPS; t++) {
        // prefetch next step's h (consumed next iteration; ~600cyc hidden)
        float hn = 0.f;
        if (c == 0 && t + 1 < TSTEPS) hn = __ldg(&Hb[(size_t)(t + 1) * UNITS + u]);

        // partial dot: 128 k-values (64 bf16x2 HFMA2), state broadcast from smem
        __nv_bfloat162 acc0 = __floats2bfloat162_rn(0.f, 0.f);
        __nv_bfloat162 acc1 = acc0;
        const uint4* sv = reinterpret_cast<const uint4*>(sm_sbf) + c * 16;
#pragma unroll
        for (int i = 0; i < 16; i++) {
            uint4 q = sv[i];
            acc0 = __hfma2(u2b(q.x), u2b(mreg[4 * i + 0]), acc0);
            acc1 = __hfma2(u2b(q.y), u2b(mreg[4 * i + 1]), acc1);
            acc0 = __hfma2(u2b(q.z), u2b(mreg[4 * i + 2]), acc0);
            acc1 = __hfma2(u2b(q.w), u2b(mreg[4 * i + 3]), acc1);
        }
        float partial = __bfloat162float(acc0.x) + __bfloat162float(acc0.y) +
                        __bfloat162float(acc1.x) + __bfloat162float(acc1.y);

        if (c) sm_part[u] = partial;
        __syncthreads();

        if (!c) {
            float z = partial + sm_part[u] + hcur;
            s += EPS_ * tanhf(z);
            Hb[(size_t)t * UNITS + u] = s;                       // overwrite h_t with state_t
            reinterpret_cast<__nv_bfloat16*>(sm_sbf)[u] = __float2bfloat16(s);
            hcur = hn;
        }
        __syncthreads();
    }
}

// ---------------------------------------------------------------------------
extern "C" void kernel_launch(void* const* d_in, const int* in_sizes, int n_in,
                              void* d_out, int out_size) {
    const float* x    = (const float*)d_in[0];
    const float* V    = (const float*)d_in[1];
    const float* W    = (const float*)d_in[2];
    const float* bias = (const float*)d_in[3];
    const float* x0   = (const float*)d_in[4];
    float* out = (float*)d_out;

    prep_M_kernel<<<UNITS / 2, UNITS>>>(W);
    proj_kernel<<<dim3(UNITS / 128, (BATCH * TSTEPS) / 128), 256>>>(x, V, bias, out);
    rnn_kernel<<<BATCH, 512>>>(out, x0);
}

// round 2
// speedup vs baseline: 1.3304x; 1.3304x over previous
#include <cuda_runtime.h>
#include <cuda_bf16.h>
#include <cstdint>

#define UNITS  256
#define FT     128
#define BATCH  32
#define TSTEPS 2048
#define EPS_   0.01f
#define GAMMA_ 0.01f

// int8-quantized off-diagonal M, packed 4 k's per uint32, k-major for coalescing:
// g_Mi8[j*UNITS + u] = bytes (M[4j,u], M[4j+1,u], M[4j+2,u], M[4j+3,u]) / g_Msc[u]
__device__ uint32_t g_Mi8[(UNITS / 4) * UNITS];   // 64 KB
__device__ float    g_Msc[UNITS];                 // per-column scale

// State quantization scale (|s| stays ~<0.2; 2x safety margin)
#define S_CLAMP 0.4375f
#define S_SCALE (S_CLAMP / 127.0f)

// ---------------------------------------------------------------------------
// Kernel 0: build per-column int8 quantized M (off-diagonal only).
// grid: 256 blocks (u = column), 256 threads (k = row)
// ---------------------------------------------------------------------------
__global__ void prep_M_kernel(const float* __restrict__ W) {
    const int u = blockIdx.x;
    const int k = threadIdx.x;

    float v = W[k * UNITS + u] - W[u * UNITS + k];
    if (k == u) v = 0.f;   // diagonal (-gamma) handled exactly in fp32 in rnn

    __shared__ float red[UNITS];
    __shared__ int   qarr[UNITS];

    red[k] = fabsf(v);
    __syncthreads();
#pragma unroll
    for (int off = 128; off > 0; off >>= 1) {
        if (k < off) red[k] = fmaxf(red[k], red[k + off]);
        __syncthreads();
    }
    const float colmax = fmaxf(red[0], 1e-30f);
    const float scale  = colmax / 127.0f;

    int qi = __float2int_rn(v / scale);
    qi = max(-127, min(127, qi));
    qarr[k] = qi;
    __syncthreads();

    if (k < UNITS / 4) {
        uint32_t p = (uint32_t)(qarr[4 * k + 0] & 255)
                   | ((uint32_t)(qarr[4 * k + 1] & 255) << 8)
                   | ((uint32_t)(qarr[4 * k + 2] & 255) << 16)
                   | ((uint32_t)(qarr[4 * k + 3] & 255) << 24);
        g_Mi8[k * UNITS + u] = p;
    }
    if (k == 0) g_Msc[u] = scale;
}

// ---------------------------------------------------------------------------
// Kernel 1: H = x @ V + bias, written in-place into d_out.
// fp32, 128x128 tile per CTA, 8x8 micro-tile per thread, K chunked by 32.
// grid: (2, 512), 256 threads
// ---------------------------------------------------------------------------
#define PT_KC 32
__global__ __launch_bounds__(256) void proj_kernel(const float* __restrict__ X,
                                                   const float* __restrict__ V,
                                                   const float* __restrict__ bias,
                                                   float* __restrict__ H) {
    __shared__ float As[PT_KC][129];
    __shared__ float Bs[PT_KC][129];

    const int tid = threadIdx.x;
    const int tx  = tid & 15;
    const int ty  = tid >> 4;
    const int r0  = blockIdx.y * 128;
    const int n0  = blockIdx.x * 128;

    float bv[8];
#pragma unroll
    for (int j = 0; j < 8; j++) bv[j] = __ldg(&bias[n0 + tx * 8 + j]);

    float acc[8][8];
#pragma unroll
    for (int i = 0; i < 8; i++)
#pragma unroll
        for (int j = 0; j < 8; j++) acc[i][j] = 0.f;

    for (int kc = 0; kc < FT; kc += PT_KC) {
        {
            const int row   = tid >> 1;
            const int kbase = (tid & 1) * 16;
            const float4* src =
                reinterpret_cast<const float4*>(&X[(size_t)(r0 + row) * FT + kc + kbase]);
#pragma unroll
            for (int i = 0; i < 4; i++) {
                float4 v4 = src[i];
                int kk = kbase + 4 * i;
                As[kk + 0][row] = v4.x;
                As[kk + 1][row] = v4.y;
                As[kk + 2][row] = v4.z;
                As[kk + 3][row] = v4.w;
            }
        }
        {
            const int kr = tid >> 3;
            const int cb = (tid & 7) * 16;
            const float4* src =
                reinterpret_cast<const float4*>(&V[(size_t)(kc + kr) * UNITS + n0 + cb]);
#pragma unroll
            for (int i = 0; i < 4; i++) {
                float4 v4 = src[i];
                Bs[kr][cb + 4 * i + 0] = v4.x;
                Bs[kr][cb + 4 * i + 1] = v4.y;
                Bs[kr][cb + 4 * i + 2] = v4.z;
                Bs[kr][cb + 4 * i + 3] = v4.w;
            }
        }
        __syncthreads();

#pragma unroll
        for (int k = 0; k < PT_KC; k++) {
            float a[8], bb[8];
#pragma unroll
            for (int i = 0; i < 8; i++) a[i] = As[k][ty * 8 + i];
#pragma unroll
            for (int j = 0; j < 8; j++) bb[j] = Bs[k][tx * 8 + j];
#pragma unroll
            for (int i = 0; i < 8; i++)
#pragma unroll
                for (int j = 0; j < 8; j++)
                    acc[i][j] = fmaf(a[i], bb[j], acc[i][j]);
        }
        __syncthreads();
    }

#pragma unroll
    for (int i = 0; i < 8; i++) {
        float* dst = &H[(size_t)(r0 + ty * 8 + i) * UNITS + n0 + tx * 8];
        float4 o0, o1;
        o0.x = acc[i][0] + bv[0]; o0.y = acc[i][1] + bv[1];
        o0.z = acc[i][2] + bv[2]; o0.w = acc[i][3] + bv[3];
        o1.x = acc[i][4] + bv[4]; o1.y = acc[i][5] + bv[5];
        o1.z = acc[i][6] + bv[6]; o1.w = acc[i][7] + bv[7];
        reinterpret_cast<float4*>(dst)[0] = o0;
        reinterpret_cast<float4*>(dst)[1] = o1;
    }
}

// ---------------------------------------------------------------------------
// Kernel 2: sequential recurrence, one CTA per batch element.
// 256 threads; thread u owns M column u as 64 packed-int8 uint32 registers and
// computes its FULL 256-k dot with DP4A (4 independent chains). State lives in
// smem as a double-buffered packed int8 vector (64 uint32). One barrier/step.
// Exact parts in fp32: z = h - gamma*s + Sm*Ss*dot_int; s += eps*tanh(z).
// ---------------------------------------------------------------------------
__global__ __launch_bounds__(256, 1) void rnn_kernel(float* __restrict__ HS,
                                                     const float* __restrict__ x0) {
    __shared__ uint32_t s_pack[2][UNITS / 4];   // double-buffered packed int8 state

    const int u = threadIdx.x;
    const int b = blockIdx.x;
    float* Hb = HS + (size_t)b * TSTEPS * UNITS;

    // M column (coalesced: j-major layout)
    int mi[64];
#pragma unroll
    for (int j = 0; j < 64; j++)
        mi[j] = (int)g_Mi8[j * UNITS + u];

    const float dot_scale = g_Msc[u] * S_SCALE;
    const float inv_ss    = 1.0f / S_SCALE;

    float s = x0[u];

    // init packed state buffer 0
    {
        int qi = __float2int_rn(s * inv_ss);
        qi = max(-127, min(127, qi));
        reinterpret_cast<char*>(&s_pack[0][0])[u] = (char)qi;
    }

    // h prefetch pipeline, depth 2
    float h0 = __ldg(&Hb[u]);
    float h1 = __ldg(&Hb[UNITS + u]);
    __syncthreads();

    for (int t = 0; t < TSTEPS; t++) {
        float h2 = (t + 2 < TSTEPS) ? __ldg(&Hb[(size_t)(t + 2) * UNITS + u]) : 0.f;

        const int r = t & 1;
        const uint4* sp = reinterpret_cast<const uint4*>(&s_pack[r][0]);

        int a0 = 0, a1 = 0, a2 = 0, a3 = 0;
#pragma unroll
        for (int i = 0; i < 16; i++) {
            uint4 q = sp[i];
            a0 = __dp4a(mi[4 * i + 0], (int)q.x, a0);
            a1 = __dp4a(mi[4 * i + 1], (int)q.y, a1);
            a2 = __dp4a(mi[4 * i + 2], (int)q.z, a2);
            a3 = __dp4a(mi[4 * i + 3], (int)q.w, a3);
        }
        float dot = (float)((a0 + a1) + (a2 + a3)) * dot_scale;

        float z = h0 + dot - GAMMA_ * s;

        // accurate fast tanh: (e^{2z}-1)/(e^{2z}+1), z clamped for safety
        float zc = fminf(fmaxf(z, -8.f), 8.f);
        float ez = __expf(2.f * zc);
        float th = __fdividef(ez - 1.f, ez + 1.f);

        s += EPS_ * th;

        Hb[(size_t)t * UNITS + u] = s;   // overwrite h_t with state_t

        // quantize new state into the other buffer
        int qi = __float2int_rn(s * inv_ss);
        qi = max(-127, min(127, qi));
        reinterpret_cast<char*>(&s_pack[1 - r][0])[u] = (char)qi;

        h0 = h1; h1 = h2;
        __syncthreads();
    }
}

// ---------------------------------------------------------------------------
extern "C" void kernel_launch(void* const* d_in, const int* in_sizes, int n_in,
                              void* d_out, int out_size) {
    const float* x    = (const float*)d_in[0];
    const float* V    = (const float*)d_in[1];
    const float* W    = (const float*)d_in[2];
    const float* bias = (const float*)d_in[3];
    const float* x0   = (const float*)d_in[4];
    float* out = (float*)d_out;

    prep_M_kernel<<<UNITS, UNITS>>>(W);
    proj_kernel<<<dim3(UNITS / 128, (BATCH * TSTEPS) / 128), 256>>>(x, V, bias, out);
    rnn_kernel<<<BATCH, 256>>>(out, x0);
}

// round 5
// speedup vs baseline: 1.7206x; 1.2933x over previous
#include <cuda_runtime.h>
#include <cuda_bf16.h>
#include <cstdint>

#define UNITS  256
#define FT     128
#define BATCH  32
#define TSTEPS 2048
#define EPS_   0.01f
#define GAMMA_ 0.01f

#define RNN_CTAS  32
#define PROJ_CTAS 116
#define N_TILES   1024     // 512 row-blocks x 2 n-halves
#define N_CHUNKS  16       // 2048 / 128 timesteps per chunk

// int8-quantized off-diagonal M, packed 4 k's per uint32, k-major:
__device__ uint32_t g_Mi8[(UNITS / 4) * UNITS];   // 64 KB
__device__ float    g_Msc[UNITS];
__device__ int      g_cnt[512];                   // per (tblk, b) completion count (==2 when ready)

#define S_CLAMP 0.4375f
#define S_SCALE (S_CLAMP / 127.0f)

// ---------------------------------------------------------------------------
// Kernel 0: quantize M per-column; zero the readiness flags (every launch).
// grid: 256 blocks (u = column), 256 threads (k = row)
// ---------------------------------------------------------------------------
__global__ void prep_M_kernel(const float* __restrict__ W) {
    const int u = blockIdx.x;
    const int k = threadIdx.x;

    if (blockIdx.x == 0) {
        g_cnt[k] = 0;
        g_cnt[k + 256] = 0;
    }

    float v = W[k * UNITS + u] - W[u * UNITS + k];
    if (k == u) v = 0.f;   // diagonal (-gamma) applied exactly in fp32

    __shared__ float red[UNITS];
    __shared__ int   qarr[UNITS];

    red[k] = fabsf(v);
    __syncthreads();
#pragma unroll
    for (int off = 128; off > 0; off >>= 1) {
        if (k < off) red[k] = fmaxf(red[k], red[k + off]);
        __syncthreads();
    }
    const float scale = fmaxf(red[0], 1e-30f) / 127.0f;

    int qi = __float2int_rn(v / scale);
    qi = max(-127, min(127, qi));
    qarr[k] = qi;
    __syncthreads();

    if (k < UNITS / 4) {
        uint32_t p = (uint32_t)(qarr[4 * k + 0] & 255)
                   | ((uint32_t)(qarr[4 * k + 1] & 255) << 8)
                   | ((uint32_t)(qarr[4 * k + 2] & 255) << 16)
                   | ((uint32_t)(qarr[4 * k + 3] & 255) << 24);
        g_Mi8[k * UNITS + u] = p;
    }
    if (k == 0) g_Msc[u] = scale;
}

// ---------------------------------------------------------------------------
// Proj tile: 128x128 fp32 GEMM tile of H = x@V + bias.
// ---------------------------------------------------------------------------
#define PT_KC 32
__device__ __forceinline__ void proj_tile(const float* __restrict__ X,
                                          const float* __restrict__ V,
                                          const float* __restrict__ bias,
                                          float* __restrict__ H,
                                          int r0, int n0,
                                          float (*As)[129], float (*Bs)[129]) {
    const int tid = threadIdx.x;
    const int tx  = tid & 15;
    const int ty  = tid >> 4;

    float bv[8];
#pragma unroll
    for (int j = 0; j < 8; j++) bv[j] = __ldg(&bias[n0 + tx * 8 + j]);

    float acc[8][8];
#pragma unroll
    for (int i = 0; i < 8; i++)
#pragma unroll
        for (int j = 0; j < 8; j++) acc[i][j] = 0.f;

    for (int kc = 0; kc < FT; kc += PT_KC) {
        {
            const int row   = tid >> 1;
            const int kbase = (tid & 1) * 16;
            const float4* src =
                reinterpret_cast<const float4*>(&X[(size_t)(r0 + row) * FT + kc + kbase]);
#pragma unroll
            for (int i = 0; i < 4; i++) {
                float4 v4 = src[i];
                int kk = kbase + 4 * i;
                As[kk + 0][row] = v4.x;
                As[kk + 1][row] = v4.y;
                As[kk + 2][row] = v4.z;
                As[kk + 3][row] = v4.w;
            }
        }
        {
            const int kr = tid >> 3;
            const int cb = (tid & 7) * 16;
            const float4* src =
                reinterpret_cast<const float4*>(&V[(size_t)(kc + kr) * UNITS + n0 + cb]);
#pragma unroll
            for (int i = 0; i < 4; i++) {
                float4 v4 = src[i];
                Bs[kr][cb + 4 * i + 0] = v4.x;
                Bs[kr][cb + 4 * i + 1] = v4.y;
                Bs[kr][cb + 4 * i + 2] = v4.z;
                Bs[kr][cb + 4 * i + 3] = v4.w;
            }
        }
        __syncthreads();

#pragma unroll
        for (int k = 0; k < PT_KC; k++) {
            float a[8], bb[8];
#pragma unroll
            for (int i = 0; i < 8; i++) a[i] = As[k][ty * 8 + i];
#pragma unroll
            for (int j = 0; j < 8; j++) bb[j] = Bs[k][tx * 8 + j];
#pragma unroll
            for (int i = 0; i < 8; i++)
#pragma unroll
                for (int j = 0; j < 8; j++)
                    acc[i][j] = fmaf(a[i], bb[j], acc[i][j]);
        }
        __syncthreads();
    }

#pragma unroll
    for (int i = 0; i < 8; i++) {
        float* dst = &H[(size_t)(r0 + ty * 8 + i) * UNITS + n0 + tx * 8];
        float4 o0, o1;
        o0.x = acc[i][0] + bv[0]; o0.y = acc[i][1] + bv[1];
        o0.z = acc[i][2] + bv[2]; o0.w = acc[i][3] + bv[3];
        o1.x = acc[i][4] + bv[4]; o1.y = acc[i][5] + bv[5];
        o1.z = acc[i][6] + bv[6]; o1.w = acc[i][7] + bv[7];
        reinterpret_cast<float4*>(dst)[0] = o0;
        reinterpret_cast<float4*>(dst)[1] = o1;
    }
}

// ---------------------------------------------------------------------------
// Fused kernel: CTAs [0,32) run the recurrence (one per batch); CTAs [32,148)
// run proj tiles persistently, t-block-major so early timesteps are produced
// first. rnn waits per 128-step chunk via release/acquire flags.
// Consumer h loads use ld.global.cg (L2 coherence point) — NEVER .nc, since
// the data is produced by other CTAs during this kernel.
// ---------------------------------------------------------------------------
__global__ __launch_bounds__(256, 1) void fused_kernel(const float* __restrict__ X,
                                                       const float* __restrict__ V,
                                                       const float* __restrict__ bias,
                                                       float* __restrict__ HS,
                                                       const float* __restrict__ x0) {
    __shared__ float smem[2 * PT_KC * 129];   // proj tiles reuse; rnn uses a corner

    if (blockIdx.x >= RNN_CTAS) {
        // ---------------- projection producer ----------------
        float (*As)[129] = reinterpret_cast<float(*)[129]>(smem);
        float (*Bs)[129] = reinterpret_cast<float(*)[129]>(smem + PT_KC * 129);
        for (int j = (int)blockIdx.x - RNN_CTAS; j < N_TILES; j += PROJ_CTAS) {
            const int n0   = (j & 1) * 128;
            const int g    = j >> 1;            // (tblk, b)
            const int tblk = g >> 5;
            const int b    = g & 31;
            const int r0   = (b * 16 + tblk) * 128;
            proj_tile(X, V, bias, HS, r0, n0, As, Bs);
            __threadfence();
            __syncthreads();
            if (threadIdx.x == 0) {
                // release-scoped increment of the readiness flag
                asm volatile("red.release.gpu.global.add.u32 [%0], %1;"
                             :: "l"(&g_cnt[g]), "r"(1) : "memory");
            }
            __syncthreads();
        }
        return;
    }

    // ---------------- recurrence consumer ----------------
    uint32_t* s_pack = reinterpret_cast<uint32_t*>(smem);   // [2][64]

    const int u = threadIdx.x;
    const int b = blockIdx.x;
    float* Hb = HS + (size_t)b * TSTEPS * UNITS;

    int mi[64];
#pragma unroll
    for (int j = 0; j < 64; j++)
        mi[j] = (int)g_Mi8[j * UNITS + u];

    const float dot_scale = g_Msc[u] * S_SCALE;
    const float inv_ss    = 1.0f / S_SCALE;

    float s = x0[u];
    {
        float sc = fminf(fmaxf(s, -S_CLAMP), S_CLAMP);
        float fq = fmaf(sc, inv_ss, 12582912.f);           // round-to-nearest magic
        reinterpret_cast<char*>(s_pack)[u] = (char)__float_as_uint(fq);
    }
    __syncthreads();

    float h0 = 0.f, h1 = 0.f;

    for (int c = 0; c < N_CHUNKS; c++) {
        // wait for this chunk's H rows (both n-halves done => cnt == 2)
        if (threadIdx.x == 0) {
            const int* flag = &g_cnt[c * 32 + b];
            unsigned v;
            do {
                asm volatile("ld.acquire.gpu.b32 %0, [%1];" : "=r"(v) : "l"(flag) : "memory");
            } while (v < 2u);
        }
        __syncthreads();

        const int tbase = c * 128;
        h0 = __ldcg(&Hb[(size_t)tbase * UNITS + u]);
        h1 = __ldcg(&Hb[(size_t)(tbase + 1) * UNITS + u]);

        for (int tt = 0; tt < 128; tt++) {
            const int t = tbase + tt;
            float h2 = (tt + 2 < 128) ? __ldcg(&Hb[(size_t)(t + 2) * UNITS + u]) : 0.f;

            const int r = t & 1;
            const uint4* sp = reinterpret_cast<const uint4*>(s_pack + r * 64);

            int a0 = 0, a1 = 0, a2 = 0, a3 = 0;
#pragma unroll
            for (int i = 0; i < 16; i++) {
                uint4 q = sp[i];
                a0 = __dp4a(mi[4 * i + 0], (int)q.x, a0);
                a1 = __dp4a(mi[4 * i + 1], (int)q.y, a1);
                a2 = __dp4a(mi[4 * i + 2], (int)q.z, a2);
                a3 = __dp4a(mi[4 * i + 3], (int)q.w, a3);
            }
            float dot = (float)((a0 + a1) + (a2 + a3)) * dot_scale;

            float z = fmaf(-GAMMA_, s, h0) + dot;

            // exact-enough tanh: (e^{2z}-1)/(e^{2z}+1)  (r2-proven, rel_err 5e-5)
            float zc = fminf(fmaxf(z, -8.f), 8.f);
            float ez = __expf(2.f * zc);
            float th = __fdividef(ez - 1.f, ez + 1.f);

            s = fmaf(EPS_, th, s);

            // quantize new state into the other buffer (magic-number round)
            float sc = fminf(fmaxf(s, -S_CLAMP), S_CLAMP);
            float fq = fmaf(sc, inv_ss, 12582912.f);
            reinterpret_cast<char*>(s_pack + (1 - r) * 64)[u] = (char)__float_as_uint(fq);

            __syncthreads();

            Hb[(size_t)t * UNITS + u] = s;   // overwrite h_t with state_t (overlaps next dot)
            h0 = h1; h1 = h2;
        }
    }
}

// ---------------------------------------------------------------------------
extern "C" void kernel_launch(void* const* d_in, const int* in_sizes, int n_in,
                              void* d_out, int out_size) {
    const float* x    = (const float*)d_in[0];
    const float* V    = (const float*)d_in[1];
    const float* W    = (const float*)d_in[2];
    const float* bias = (const float*)d_in[3];
    const float* x0   = (const float*)d_in[4];
    float* out = (float*)d_out;

    prep_M_kernel<<<UNITS, UNITS>>>(W);
    fused_kernel<<<RNN_CTAS + PROJ_CTAS, 256>>>(x, V, bias, out, x0);
}